// round 3
// baseline (speedup 1.0000x reference)
#include <cuda_runtime.h>

#define B_   4
#define S_   2048
#define D_   1024
#define H_   16
#define HD   64
#define ROWS (B_*S_)          // 8192
#define NEG_BIG (-1e9f)

// Scratch (allocation-free): 4 x 32MB in module .bss
__device__ float g_Qh[(size_t)B_*H_*S_*HD];
__device__ float g_Kh[(size_t)B_*H_*S_*HD];
__device__ float g_Vh[(size_t)B_*H_*S_*HD];
__device__ float g_ctx[(size_t)ROWS*D_];

// ---------------------------------------------------------------------------
// Fused QKV projection: O = X @ W^T  (X [8192,1024], W [1024,1024] row-major,
// inner dim contiguous in both => NT gemm). Epilogue remaps to [b,h,s,hd]
// and folds the 1/sqrt(64) scale into Q.
// 64x64 tile, BK=16, 16x16 threads, 4x4 per thread.
// ---------------------------------------------------------------------------
__global__ __launch_bounds__(256) void proj_kernel(
    const float* __restrict__ Xq, const float* __restrict__ Xk, const float* __restrict__ Xv,
    const float* __restrict__ Wq, const float* __restrict__ Wk, const float* __restrict__ Wv)
{
    __shared__ float As[16][68];
    __shared__ float Bs[16][68];

    const int z = blockIdx.z;
    const float* X = (z == 0) ? Xq : ((z == 1) ? Xk : Xv);
    const float* W = (z == 0) ? Wq : ((z == 1) ? Wk : Wv);
    float*       O = (z == 0) ? g_Qh : ((z == 1) ? g_Kh : g_Vh);
    const float scale = (z == 0) ? 0.125f : 1.0f;

    const int m0 = blockIdx.y * 64;
    const int n0 = blockIdx.x * 64;
    const int t  = threadIdx.x;
    const int tx = t & 15, ty = t >> 4;
    const int lr = t >> 2, lq = t & 3;    // loader: row-in-tile, float4-in-row

    float acc[4][4];
#pragma unroll
    for (int r = 0; r < 4; r++)
#pragma unroll
        for (int c = 0; c < 4; c++) acc[r][c] = 0.f;

    const float* Ap = X + (size_t)(m0 + lr) * D_ + lq * 4;
    const float* Bp = W + (size_t)(n0 + lr) * D_ + lq * 4;

    for (int kt = 0; kt < D_; kt += 16) {
        float4 a = *(const float4*)(Ap + kt);
        float4 b = *(const float4*)(Bp + kt);
        __syncthreads();
        As[lq * 4 + 0][lr] = a.x; As[lq * 4 + 1][lr] = a.y;
        As[lq * 4 + 2][lr] = a.z; As[lq * 4 + 3][lr] = a.w;
        Bs[lq * 4 + 0][lr] = b.x; Bs[lq * 4 + 1][lr] = b.y;
        Bs[lq * 4 + 2][lr] = b.z; Bs[lq * 4 + 3][lr] = b.w;
        __syncthreads();
#pragma unroll
        for (int kk = 0; kk < 16; kk++) {
            float4 av = *(const float4*)&As[kk][ty * 4];
            float4 bv = *(const float4*)&Bs[kk][tx * 4];
            float aa[4] = {av.x, av.y, av.z, av.w};
            float bb[4] = {bv.x, bv.y, bv.z, bv.w};
#pragma unroll
            for (int r = 0; r < 4; r++)
#pragma unroll
                for (int c = 0; c < 4; c++) acc[r][c] += aa[r] * bb[c];
        }
    }

    const int h = n0 >> 6;   // tile spans exactly one head
#pragma unroll
    for (int r = 0; r < 4; r++) {
        int row = m0 + ty * 4 + r;
        int bb  = row >> 11;        // / 2048
        int s   = row & 2047;
        float4 o = make_float4(acc[r][0] * scale, acc[r][1] * scale,
                               acc[r][2] * scale, acc[r][3] * scale);
        *(float4*)&O[((size_t)(bb * H_ + h) * S_ + s) * HD + tx * 4] = o;
    }
}

// ---------------------------------------------------------------------------
// Flash attention. One block = (b,h, 64-query tile). KV loop capped at
// min(q0+64, sen_len[b]) — keys >= sen_len are masked for every query, and
// j=0 is always valid (sen_len >= 1), so clipping is numerically exact.
// Dynamic smem: QsT[64d][68] | KsT/PsT[64][68] | Vs[64k][68] = 52224 B.
// ---------------------------------------------------------------------------
__global__ __launch_bounds__(256) void attn_kernel(const int* __restrict__ sen_len)
{
    extern __shared__ float sm[];
    float* QsT = sm;               // [d][q]  (transposed)
    float* KP  = sm + 64 * 68;     // phase1: KsT [d][k]; phase2: PsT [k][q]
    float* Vs  = sm + 2 * 64 * 68; // [k][d]

    const int bh = blockIdx.y;
    const int b  = bh >> 4;
    const int h  = bh & 15;
    const int q0 = blockIdx.x * 64;
    const float* Qg = g_Qh + (size_t)bh * S_ * HD;
    const float* Kg = g_Kh + (size_t)bh * S_ * HD;
    const float* Vg = g_Vh + (size_t)bh * S_ * HD;
    const int sen    = sen_len[b];
    const int kv_len = min(q0 + 64, sen);

    const int t  = threadIdx.x;
    const int tx = t & 15, ty = t >> 4;

    // Load Q tile transposed (scale already folded in by proj_kernel)
#pragma unroll
    for (int it = 0; it < 4; it++) {
        int idx = t + it * 256;
        int row = idx >> 4, dq = idx & 15;
        float4 v = *(const float4*)&Qg[(size_t)(q0 + row) * HD + dq * 4];
        QsT[(dq * 4 + 0) * 68 + row] = v.x; QsT[(dq * 4 + 1) * 68 + row] = v.y;
        QsT[(dq * 4 + 2) * 68 + row] = v.z; QsT[(dq * 4 + 3) * 68 + row] = v.w;
    }

    float m[4], l[4], o[4][4];
#pragma unroll
    for (int r = 0; r < 4; r++) {
        m[r] = NEG_BIG; l[r] = 0.f;
#pragma unroll
        for (int c = 0; c < 4; c++) o[r][c] = 0.f;
    }

    for (int k0 = 0; k0 < kv_len; k0 += 64) {
        __syncthreads();   // Q visible; previous phase-2 reads of KP/Vs done
#pragma unroll
        for (int it = 0; it < 4; it++) {
            int idx = t + it * 256;
            int row = idx >> 4, dq = idx & 15;
            float4 kv = *(const float4*)&Kg[(size_t)(k0 + row) * HD + dq * 4];
            KP[(dq * 4 + 0) * 68 + row] = kv.x; KP[(dq * 4 + 1) * 68 + row] = kv.y;
            KP[(dq * 4 + 2) * 68 + row] = kv.z; KP[(dq * 4 + 3) * 68 + row] = kv.w;
            float4 vv = *(const float4*)&Vg[(size_t)(k0 + row) * HD + dq * 4];
            *(float4*)&Vs[row * 68 + dq * 4] = vv;
        }
        __syncthreads();

        // S = Q @ K^T (scale pre-folded). rows = queries ty*4+r, cols = keys tx*4+c
        float s[4][4];
#pragma unroll
        for (int r = 0; r < 4; r++)
#pragma unroll
            for (int c = 0; c < 4; c++) s[r][c] = 0.f;
#pragma unroll 8
        for (int dd = 0; dd < 64; dd++) {
            float4 av = *(const float4*)&QsT[dd * 68 + ty * 4];
            float4 bv = *(const float4*)&KP[dd * 68 + tx * 4];
            float aa[4] = {av.x, av.y, av.z, av.w};
            float bb[4] = {bv.x, bv.y, bv.z, bv.w};
#pragma unroll
            for (int r = 0; r < 4; r++)
#pragma unroll
                for (int c = 0; c < 4; c++) s[r][c] += aa[r] * bb[c];
        }

        // causal + padding mask (matches reference -1e9 semantics)
#pragma unroll
        for (int r = 0; r < 4; r++) {
            int i = q0 + ty * 4 + r;
#pragma unroll
            for (int c = 0; c < 4; c++) {
                int j = k0 + tx * 4 + c;
                if (j > i || j >= sen) s[r][c] = NEG_BIG;
            }
        }

        // online softmax update (row stats reduced over the 16 tx lanes)
#pragma unroll
        for (int r = 0; r < 4; r++) {
            float tm = fmaxf(fmaxf(s[r][0], s[r][1]), fmaxf(s[r][2], s[r][3]));
            tm = fmaxf(tm, __shfl_xor_sync(0xffffffffu, tm, 1));
            tm = fmaxf(tm, __shfl_xor_sync(0xffffffffu, tm, 2));
            tm = fmaxf(tm, __shfl_xor_sync(0xffffffffu, tm, 4));
            tm = fmaxf(tm, __shfl_xor_sync(0xffffffffu, tm, 8));
            float mnew  = fmaxf(m[r], tm);
            float alpha = __expf(m[r] - mnew);
            float rsum = 0.f;
#pragma unroll
            for (int c = 0; c < 4; c++) {
                float p = __expf(s[r][c] - mnew);
                s[r][c] = p;
                rsum += p;
            }
            rsum += __shfl_xor_sync(0xffffffffu, rsum, 1);
            rsum += __shfl_xor_sync(0xffffffffu, rsum, 2);
            rsum += __shfl_xor_sync(0xffffffffu, rsum, 4);
            rsum += __shfl_xor_sync(0xffffffffu, rsum, 8);
            l[r] = l[r] * alpha + rsum;
            m[r] = mnew;
#pragma unroll
            for (int c = 0; c < 4; c++) o[r][c] *= alpha;
        }

        __syncthreads();   // all KsT reads done; safe to overwrite with PsT
#pragma unroll
        for (int r = 0; r < 4; r++)
#pragma unroll
            for (int c = 0; c < 4; c++)
                KP[(tx * 4 + c) * 68 + ty * 4 + r] = s[r][c];
        __syncthreads();

        // O += P @ V. rows = queries ty*4+r, cols = head-dim tx*4+c.
        // Masked keys have p == 0 exactly, so summing all 64 is exact.
#pragma unroll 8
        for (int kk = 0; kk < 64; kk++) {
            float4 av = *(const float4*)&KP[kk * 68 + ty * 4];
            float4 bv = *(const float4*)&Vs[kk * 68 + tx * 4];
            float aa[4] = {av.x, av.y, av.z, av.w};
            float bb[4] = {bv.x, bv.y, bv.z, bv.w};
#pragma unroll
            for (int r = 0; r < 4; r++)
#pragma unroll
                for (int c = 0; c < 4; c++) o[r][c] += aa[r] * bb[c];
        }
    }

    // finalize: ctx[b, s, h*64 + j]
#pragma unroll
    for (int r = 0; r < 4; r++) {
        float inv = 1.f / l[r];
        int i = q0 + ty * 4 + r;
        float4 ov = make_float4(o[r][0] * inv, o[r][1] * inv,
                                o[r][2] * inv, o[r][3] * inv);
        *(float4*)&g_ctx[((size_t)b * S_ + i) * D_ + h * HD + tx * 4] = ov;
    }
}

// ---------------------------------------------------------------------------
// Output projection + residual: out = ctx @ Wo^T + q
// ---------------------------------------------------------------------------
__global__ __launch_bounds__(256) void oproj_kernel(
    const float* __restrict__ Wo, const float* __restrict__ resid,
    float* __restrict__ out)
{
    __shared__ float As[16][68];
    __shared__ float Bs[16][68];

    const int m0 = blockIdx.y * 64;
    const int n0 = blockIdx.x * 64;
    const int t  = threadIdx.x;
    const int tx = t & 15, ty = t >> 4;
    const int lr = t >> 2, lq = t & 3;

    float acc[4][4];
#pragma unroll
    for (int r = 0; r < 4; r++)
#pragma unroll
        for (int c = 0; c < 4; c++) acc[r][c] = 0.f;

    const float* Ap = g_ctx + (size_t)(m0 + lr) * D_ + lq * 4;
    const float* Bp = Wo + (size_t)(n0 + lr) * D_ + lq * 4;

    for (int kt = 0; kt < D_; kt += 16) {
        float4 a = *(const float4*)(Ap + kt);
        float4 b = *(const float4*)(Bp + kt);
        __syncthreads();
        As[lq * 4 + 0][lr] = a.x; As[lq * 4 + 1][lr] = a.y;
        As[lq * 4 + 2][lr] = a.z; As[lq * 4 + 3][lr] = a.w;
        Bs[lq * 4 + 0][lr] = b.x; Bs[lq * 4 + 1][lr] = b.y;
        Bs[lq * 4 + 2][lr] = b.z; Bs[lq * 4 + 3][lr] = b.w;
        __syncthreads();
#pragma unroll
        for (int kk = 0; kk < 16; kk++) {
            float4 av = *(const float4*)&As[kk][ty * 4];
            float4 bv = *(const float4*)&Bs[kk][tx * 4];
            float aa[4] = {av.x, av.y, av.z, av.w};
            float bb[4] = {bv.x, bv.y, bv.z, bv.w};
#pragma unroll
            for (int r = 0; r < 4; r++)
#pragma unroll
                for (int c = 0; c < 4; c++) acc[r][c] += aa[r] * bb[c];
        }
    }

#pragma unroll
    for (int r = 0; r < 4; r++) {
        int row = m0 + ty * 4 + r;
        int col = n0 + tx * 4;
        float4 rv = *(const float4*)&resid[(size_t)row * D_ + col];
        float4 ov = make_float4(acc[r][0] + rv.x, acc[r][1] + rv.y,
                                acc[r][2] + rv.z, acc[r][3] + rv.w);
        *(float4*)&out[(size_t)row * D_ + col] = ov;
    }
}

// ---------------------------------------------------------------------------
// LayerNorm (biased variance) in place on out. One block per 1024-elem row.
// ---------------------------------------------------------------------------
__global__ __launch_bounds__(256) void ln_kernel(
    float* __restrict__ out, const float* __restrict__ gamma,
    const float* __restrict__ beta)
{
    __shared__ float sbuf[8], ssbuf[8], red[2];
    const int row = blockIdx.x;
    float* p = out + (size_t)row * D_;
    const int t = threadIdx.x;

    float4 x = *(const float4*)&p[t * 4];
    float s  = x.x + x.y + x.z + x.w;
    float ss = x.x * x.x + x.y * x.y + x.z * x.z + x.w * x.w;
#pragma unroll
    for (int off = 16; off; off >>= 1) {
        s  += __shfl_xor_sync(0xffffffffu, s, off);
        ss += __shfl_xor_sync(0xffffffffu, ss, off);
    }
    if ((t & 31) == 0) { sbuf[t >> 5] = s; ssbuf[t >> 5] = ss; }
    __syncthreads();
    if (t == 0) {
        float S = 0.f, SS = 0.f;
        for (int i = 0; i < 8; i++) { S += sbuf[i]; SS += ssbuf[i]; }
        red[0] = S; red[1] = SS;
    }
    __syncthreads();
    float mean = red[0] * (1.f / 1024.f);
    float var  = red[1] * (1.f / 1024.f) - mean * mean;
    float inv  = rsqrtf(var + 1e-5f);

    float4 g  = *(const float4*)&gamma[t * 4];
    float4 bb = *(const float4*)&beta[t * 4];
    float4 y;
    y.x = (x.x - mean) * inv * g.x + bb.x;
    y.y = (x.y - mean) * inv * g.y + bb.y;
    y.z = (x.z - mean) * inv * g.z + bb.z;
    y.w = (x.w - mean) * inv * g.w + bb.w;
    *(float4*)&p[t * 4] = y;
}

// ---------------------------------------------------------------------------
extern "C" void kernel_launch(void* const* d_in, const int* in_sizes, int n_in,
                              void* d_out, int out_size)
{
    const float* q     = (const float*)d_in[0];
    const float* k     = (const float*)d_in[1];
    const float* v     = (const float*)d_in[2];
    const float* Wq    = (const float*)d_in[3];
    const float* Wk    = (const float*)d_in[4];
    const float* Wv    = (const float*)d_in[5];
    const float* Wo    = (const float*)d_in[6];
    const float* gamma = (const float*)d_in[7];
    const float* beta  = (const float*)d_in[8];
    const int*   sen   = (const int*)d_in[9];
    float* out = (float*)d_out;

    const int ATTN_SMEM = 3 * 64 * 68 * (int)sizeof(float);  // 52224 B > 48K
    cudaFuncSetAttribute(attn_kernel,
                         cudaFuncAttributeMaxDynamicSharedMemorySize, ATTN_SMEM);

    proj_kernel<<<dim3(16, 128, 3), 256>>>(q, k, v, Wq, Wk, Wv);
    attn_kernel<<<dim3(S_ / 64, B_ * H_), 256, ATTN_SMEM>>>(sen);
    oproj_kernel<<<dim3(16, 128), 256>>>(Wo, q, out);
    ln_kernel<<<ROWS, 256>>>(out, gamma, beta);
}